// round 1
// baseline (speedup 1.0000x reference)
#include <cuda_runtime.h>
#include <math.h>

#define HH 128
#define WW 128
#define CIN 64
#define COUT 64
#define BB 2
#define KT 9
#define HW (HH*WW)

// ---------------- scratch (device globals; no allocation) ----------------
__device__ float g_offy[BB * KT * HW];
__device__ float g_offx[BB * KT * HW];
__device__ float g_mask[BB * KT * HW];
__device__ float g_wt[KT * CIN * COUT];   // [k][c][o], BN-scale folded
__device__ float g_bias2[COUT];

// ---------------- prep: fold BN into weights ----------------
__global__ void prep_kernel(const float* __restrict__ weight,
                            const float* __restrict__ bias,
                            const float* __restrict__ gamma,
                            const float* __restrict__ beta,
                            const float* __restrict__ run_mean,
                            const float* __restrict__ run_var) {
    int idx = blockIdx.x * blockDim.x + threadIdx.x;
    if (idx < COUT) {
        float inv = gamma[idx] * rsqrtf(run_var[idx] + 1e-5f);
        g_bias2[idx] = (bias[idx] - run_mean[idx]) * inv + beta[idx];
    }
    if (idx < KT * CIN * COUT) {
        int k = idx >> 12;            // /4096
        int c = (idx >> 6) & 63;
        int o = idx & 63;
        float inv = gamma[o] * rsqrtf(run_var[o] + 1e-5f);
        g_wt[idx] = weight[(o * CIN + c) * KT + k] * inv;
    }
}

// ---------------- offset conv: 3x3, 64 -> 27 ch, pad 1 ----------------
// 1 thread per pixel, 27(+1 pad) accumulators, weights in dyn smem [c*9+t][28]
__global__ void offset_conv_kernel(const float* __restrict__ x,
                                   const float* __restrict__ w_off,
                                   const float* __restrict__ b_off) {
    extern __shared__ float ws[];   // 576 * 28 floats = 64512 B
    int tid = threadIdx.x;

    for (int i = tid; i < 27 * CIN * 9; i += 256) {
        int oc = i / (CIN * 9);
        int rem = i - oc * (CIN * 9);
        int c = rem / 9;
        int t = rem - c * 9;
        ws[(c * 9 + t) * 28 + oc] = w_off[i];
    }
    for (int i = tid; i < 576; i += 256) ws[i * 28 + 27] = 0.0f;
    __syncthreads();

    int pid = blockIdx.x * 256 + tid;
    int b = pid >> 14;
    int h = (pid >> 7) & 127;
    int w = pid & 127;

    float acc[28];
#pragma unroll
    for (int oc = 0; oc < 27; ++oc) acc[oc] = __ldg(&b_off[oc]);
    acc[27] = 0.0f;

    const float* xb = x + b * (CIN * HW);
    for (int c = 0; c < CIN; ++c) {
        const float* xc = xb + c * HW;
        float xv[9];
#pragma unroll
        for (int ty = 0; ty < 3; ++ty) {
#pragma unroll
            for (int tx = 0; tx < 3; ++tx) {
                int hh = h + ty - 1;
                int ww = w + tx - 1;
                bool ok = (hh >= 0) & (hh < HH) & (ww >= 0) & (ww < WW);
                xv[ty * 3 + tx] = ok ? __ldg(&xc[hh * WW + ww]) : 0.0f;
            }
        }
#pragma unroll
        for (int t = 0; t < 9; ++t) {
            float v = xv[t];
            const float4* w4 = (const float4*)&ws[(c * 9 + t) * 28];
#pragma unroll
            for (int q = 0; q < 7; ++q) {
                float4 wv = w4[q];
                acc[q * 4 + 0] = fmaf(v, wv.x, acc[q * 4 + 0]);
                acc[q * 4 + 1] = fmaf(v, wv.y, acc[q * 4 + 1]);
                acc[q * 4 + 2] = fmaf(v, wv.z, acc[q * 4 + 2]);
                acc[q * 4 + 3] = fmaf(v, wv.w, acc[q * 4 + 3]);
            }
        }
    }

    int base = (b * KT) * HW + h * WW + w;
#pragma unroll
    for (int k = 0; k < KT; ++k) {
        g_offy[base + k * HW] = acc[2 * k];
        g_offx[base + k * HW] = acc[2 * k + 1];
        float z = acc[18 + k];
        g_mask[base + k * HW] = 1.0f / (1.0f + expf(-z));
    }
}

// ---------------- main: bilinear sample + 576-K GEMM + bias + relu ----------------
// block = 32 consecutive-w pixels, 256 threads
__global__ void dcn_main_kernel(const float* __restrict__ x,
                                float* __restrict__ out) {
    __shared__ float S[CIN * 32];     // [c][p]   8 KB
    __shared__ float WS[CIN * COUT];  // [c][o]  16 KB

    int tid = threadIdx.x;
    int lane = tid & 31;
    int base = blockIdx.x * 32;
    int b = base >> 14;
    int h = (base >> 7) & 127;
    int w = (base & 127) + lane;

    int p = lane;
    int og = tid >> 5;          // 0..7 : oc group (GEMM) and channel group (sampling)
    int oc0 = og * 8;

    float acc[8];
#pragma unroll
    for (int i = 0; i < 8; ++i) acc[i] = 0.0f;

    const float* xb = x + (b * CIN + og * 8) * HW;

#pragma unroll 1
    for (int k = 0; k < KT; ++k) {
        // --- per-pixel bilinear coords (each warp redundantly for its lane) ---
        int off_idx = (b * KT + k) * HW + h * WW + w;
        float oy = g_offy[off_idx];
        float ox = g_offx[off_idx];
        float m  = g_mask[off_idx];
        float py = (float)(h - 1 + k / 3) + oy;
        float px = (float)(w - 1 + k % 3) + ox;
        float y0f = floorf(py), x0f = floorf(px);
        float ly = py - y0f, lx = px - x0f;
        int y0 = (int)y0f, x0 = (int)x0f;
        float vy0 = (y0 >= 0 && y0 < HH) ? 1.0f : 0.0f;
        float vy1 = (y0 + 1 >= 0 && y0 + 1 < HH) ? 1.0f : 0.0f;
        float vx0 = (x0 >= 0 && x0 < WW) ? 1.0f : 0.0f;
        float vx1 = (x0 + 1 >= 0 && x0 + 1 < WW) ? 1.0f : 0.0f;
        float w00 = (1.0f - ly) * (1.0f - lx) * m * vy0 * vx0;
        float w01 = (1.0f - ly) * lx * m * vy0 * vx1;
        float w10 = ly * (1.0f - lx) * m * vy1 * vx0;
        float w11 = ly * lx * m * vy1 * vx1;
        int yc0 = min(max(y0, 0), HH - 1);
        int yc1 = min(max(y0 + 1, 0), HH - 1);
        int xc0 = min(max(x0, 0), WW - 1);
        int xc1 = min(max(x0 + 1, 0), WW - 1);
        int a00 = yc0 * WW + xc0;
        int a01 = yc0 * WW + xc1;
        int a10 = yc1 * WW + xc0;
        int a11 = yc1 * WW + xc1;

        // --- stage this tap's weight tile [c][o] ---
        {
            const float4* wg = (const float4*)&g_wt[k * (CIN * COUT)];
            float4* WS4 = (float4*)WS;
#pragma unroll
            for (int i = 0; i < 4; ++i) WS4[tid + i * 256] = wg[tid + i * 256];
        }

        // --- sample 8 channels per warp into S[c][p] ---
#pragma unroll
        for (int i = 0; i < 8; ++i) {
            const float* xc = xb + i * HW;
            float v = w00 * __ldg(&xc[a00]) + w01 * __ldg(&xc[a01])
                    + w10 * __ldg(&xc[a10]) + w11 * __ldg(&xc[a11]);
            S[(og * 8 + i) * 32 + lane] = v;
        }
        __syncthreads();

        // --- GEMM: acc[o] += S[c][p] * WS[c][o] ---
#pragma unroll 8
        for (int c = 0; c < CIN; ++c) {
            float s = S[c * 32 + p];
            float4 wa = *(const float4*)&WS[c * COUT + oc0];
            float4 wb = *(const float4*)&WS[c * COUT + oc0 + 4];
            acc[0] = fmaf(s, wa.x, acc[0]);
            acc[1] = fmaf(s, wa.y, acc[1]);
            acc[2] = fmaf(s, wa.z, acc[2]);
            acc[3] = fmaf(s, wa.w, acc[3]);
            acc[4] = fmaf(s, wb.x, acc[4]);
            acc[5] = fmaf(s, wb.y, acc[5]);
            acc[6] = fmaf(s, wb.z, acc[6]);
            acc[7] = fmaf(s, wb.w, acc[7]);
        }
        __syncthreads();
    }

    // --- epilogue: folded bias + relu ---
    int obase = (b * COUT + oc0) * HW + h * WW + w;
#pragma unroll
    for (int i = 0; i < 8; ++i) {
        float r = acc[i] + g_bias2[oc0 + i];
        out[obase + i * HW] = fmaxf(r, 0.0f);
    }
}

// ---------------- launch ----------------
extern "C" void kernel_launch(void* const* d_in, const int* in_sizes, int n_in,
                              void* d_out, int out_size) {
    const float* x        = (const float*)d_in[0];
    const float* w_off    = (const float*)d_in[1];
    const float* b_off    = (const float*)d_in[2];
    const float* weight   = (const float*)d_in[3];
    const float* bias     = (const float*)d_in[4];
    const float* gamma    = (const float*)d_in[5];
    const float* beta     = (const float*)d_in[6];
    const float* run_mean = (const float*)d_in[7];
    const float* run_var  = (const float*)d_in[8];
    float* out = (float*)d_out;

    prep_kernel<<<(KT * CIN * COUT + 255) / 256, 256>>>(weight, bias, gamma, beta,
                                                        run_mean, run_var);

    cudaFuncSetAttribute(offset_conv_kernel,
                         cudaFuncAttributeMaxDynamicSharedMemorySize, 576 * 28 * 4);
    offset_conv_kernel<<<(BB * HW) / 256, 256, 576 * 28 * 4>>>(x, w_off, b_off);

    dcn_main_kernel<<<(BB * HW) / 32, 256>>>(x, out);
}

// round 2
// speedup vs baseline: 1.1676x; 1.1676x over previous
#include <cuda_runtime.h>
#include <math.h>

#define HH 128
#define WW 128
#define CIN 64
#define COUT 64
#define BB 2
#define KT 9
#define HW (HH*WW)

// ---------------- scratch (device globals; no allocation) ----------------
__device__ float g_offy[BB * KT * HW];
__device__ float g_offx[BB * KT * HW];
__device__ float g_mask[BB * KT * HW];
__device__ float g_wt[KT * CIN * COUT];   // [k][c][o], BN-scale folded
__device__ float g_bias2[COUT];

// ---------------- packed f32x2 helpers ----------------
__device__ __forceinline__ unsigned long long pack2(float lo, float hi) {
    unsigned long long r;
    asm("mov.b64 %0, {%1, %2};" : "=l"(r) : "f"(lo), "f"(hi));
    return r;
}
__device__ __forceinline__ void unpack2(unsigned long long v, float& lo, float& hi) {
    asm("mov.b64 {%0, %1}, %2;" : "=f"(lo), "=f"(hi) : "l"(v));
}
__device__ __forceinline__ unsigned long long fma2(unsigned long long a,
                                                   unsigned long long b,
                                                   unsigned long long c) {
    unsigned long long d;
    asm("fma.rn.f32x2 %0, %1, %2, %3;" : "=l"(d) : "l"(a), "l"(b), "l"(c));
    return d;
}

// ---------------- prep: fold BN into weights ----------------
__global__ void prep_kernel(const float* __restrict__ weight,
                            const float* __restrict__ bias,
                            const float* __restrict__ gamma,
                            const float* __restrict__ beta,
                            const float* __restrict__ run_mean,
                            const float* __restrict__ run_var) {
    int idx = blockIdx.x * blockDim.x + threadIdx.x;
    if (idx < COUT) {
        float inv = gamma[idx] * rsqrtf(run_var[idx] + 1e-5f);
        g_bias2[idx] = (bias[idx] - run_mean[idx]) * inv + beta[idx];
    }
    if (idx < KT * CIN * COUT) {
        int k = idx >> 12;
        int c = (idx >> 6) & 63;
        int o = idx & 63;
        float inv = gamma[o] * rsqrtf(run_var[o] + 1e-5f);
        g_wt[idx] = weight[(o * CIN + c) * KT + k] * inv;
    }
}

// ---------------- offset conv: 3x3, 64 -> 27 ch, pad 1 (FFMA2) ----------------
__global__ void offset_conv_kernel(const float* __restrict__ x,
                                   const float* __restrict__ w_off,
                                   const float* __restrict__ b_off) {
    extern __shared__ float ws[];   // 576 * 28 floats = 64512 B
    int tid = threadIdx.x;

    for (int i = tid; i < 27 * CIN * 9; i += 256) {
        int oc = i / (CIN * 9);
        int rem = i - oc * (CIN * 9);
        int c = rem / 9;
        int t = rem - c * 9;
        ws[(c * 9 + t) * 28 + oc] = w_off[i];
    }
    for (int i = tid; i < 576; i += 256) ws[i * 28 + 27] = 0.0f;
    __syncthreads();

    int pid = blockIdx.x * 256 + tid;
    int b = pid >> 14;
    int h = (pid >> 7) & 127;
    int w = pid & 127;

    unsigned long long acc2[14];
#pragma unroll
    for (int q = 0; q < 14; ++q) {
        float lo = __ldg(&b_off[2 * q]);
        float hi = (2 * q + 1 < 27) ? __ldg(&b_off[2 * q + 1]) : 0.0f;
        acc2[q] = pack2(lo, hi);
    }

    const float* xb = x + b * (CIN * HW);
    for (int c = 0; c < CIN; ++c) {
        const float* xc = xb + c * HW;
        float xv[9];
#pragma unroll
        for (int ty = 0; ty < 3; ++ty) {
#pragma unroll
            for (int tx = 0; tx < 3; ++tx) {
                int hh = h + ty - 1;
                int www = w + tx - 1;
                bool ok = (hh >= 0) & (hh < HH) & (www >= 0) & (www < WW);
                xv[ty * 3 + tx] = ok ? __ldg(&xc[hh * WW + www]) : 0.0f;
            }
        }
#pragma unroll
        for (int t = 0; t < 9; ++t) {
            unsigned long long vv = pack2(xv[t], xv[t]);
            const ulonglong2* w2 = (const ulonglong2*)&ws[(c * 9 + t) * 28];
#pragma unroll
            for (int q = 0; q < 7; ++q) {
                ulonglong2 wp = w2[q];
                acc2[2 * q + 0] = fma2(vv, wp.x, acc2[2 * q + 0]);
                acc2[2 * q + 1] = fma2(vv, wp.y, acc2[2 * q + 1]);
            }
        }
    }

    float acc[28];
#pragma unroll
    for (int q = 0; q < 14; ++q) unpack2(acc2[q], acc[2 * q], acc[2 * q + 1]);

    int base = (b * KT) * HW + h * WW + w;
#pragma unroll
    for (int k = 0; k < KT; ++k) {
        g_offy[base + k * HW] = acc[2 * k];
        g_offx[base + k * HW] = acc[2 * k + 1];
        float z = acc[18 + k];
        g_mask[base + k * HW] = 1.0f / (1.0f + __expf(-z));
    }
}

// ---------------- main: bilinear sample + 576-K GEMM (FFMA2) ----------------
// block = 64 consecutive-w pixels, 256 threads, thread tile = 2 px x 8 oc
__global__ void __launch_bounds__(256) dcn_main_kernel(const float* __restrict__ x,
                                                       float* __restrict__ out) {
    __shared__ float S[CIN * 64];     // [c][p]   16 KB
    __shared__ float WS[CIN * COUT];  // [c][o]   16 KB

    int tid = threadIdx.x;
    int lane = tid & 31;
    int wid = tid >> 5;               // 0..7 : channel group for sampling
    int base = blockIdx.x * 64;
    int b = base >> 14;
    int row = (base >> 7) & 127;
    int col0 = base & 127;            // 0 or 64

    int pp = tid & 31;                // pixel-pair index (px = 2*pp, 2*pp+1)
    int ocg = tid >> 5;
    int oc0 = ocg * 8;

    unsigned long long acc[2][4];
#pragma unroll
    for (int hh = 0; hh < 2; ++hh)
#pragma unroll
        for (int q = 0; q < 4; ++q) acc[hh][q] = 0ULL;

    const float* xb = x + (b * CIN + wid * 8) * HW;

#pragma unroll 1
    for (int k = 0; k < KT; ++k) {
        // --- bilinear coords for this thread's two sampling pixels (lane, lane+32) ---
        float W00[2], W01[2], W10[2], W11[2];
        int A00[2], A01[2], A10[2], A11[2];
#pragma unroll
        for (int j = 0; j < 2; ++j) {
            int wc = col0 + lane + 32 * j;
            int off_idx = (b * KT + k) * HW + row * WW + wc;
            float oy = g_offy[off_idx];
            float ox = g_offx[off_idx];
            float m  = g_mask[off_idx];
            float py = (float)(row - 1 + k / 3) + oy;
            float px = (float)(wc - 1 + k % 3) + ox;
            float y0f = floorf(py), x0f = floorf(px);
            float ly = py - y0f, lx = px - x0f;
            int y0 = (int)y0f, x0 = (int)x0f;
            float vy0 = (y0 >= 0 && y0 < HH) ? 1.0f : 0.0f;
            float vy1 = (y0 + 1 >= 0 && y0 + 1 < HH) ? 1.0f : 0.0f;
            float vx0 = (x0 >= 0 && x0 < WW) ? 1.0f : 0.0f;
            float vx1 = (x0 + 1 >= 0 && x0 + 1 < WW) ? 1.0f : 0.0f;
            W00[j] = (1.0f - ly) * (1.0f - lx) * m * vy0 * vx0;
            W01[j] = (1.0f - ly) * lx * m * vy0 * vx1;
            W10[j] = ly * (1.0f - lx) * m * vy1 * vx0;
            W11[j] = ly * lx * m * vy1 * vx1;
            int yc0 = min(max(y0, 0), HH - 1);
            int yc1 = min(max(y0 + 1, 0), HH - 1);
            int xc0 = min(max(x0, 0), WW - 1);
            int xc1 = min(max(x0 + 1, 0), WW - 1);
            A00[j] = yc0 * WW + xc0;
            A01[j] = yc0 * WW + xc1;
            A10[j] = yc1 * WW + xc0;
            A11[j] = yc1 * WW + xc1;
        }

        // --- stage this tap's weight tile [c][o] ---
        {
            const float4* wg = (const float4*)&g_wt[k * (CIN * COUT)];
            float4* WS4 = (float4*)WS;
#pragma unroll
            for (int i = 0; i < 4; ++i) WS4[tid + i * 256] = wg[tid + i * 256];
        }

        // --- sample 8 channels x 2 pixel-halves per thread into S[c][p] ---
#pragma unroll
        for (int i = 0; i < 8; ++i) {
            const float* xc = xb + i * HW;
#pragma unroll
            for (int j = 0; j < 2; ++j) {
                float v = W00[j] * __ldg(&xc[A00[j]]) + W01[j] * __ldg(&xc[A01[j]])
                        + W10[j] * __ldg(&xc[A10[j]]) + W11[j] * __ldg(&xc[A11[j]]);
                S[(wid * 8 + i) * 64 + lane + 32 * j] = v;
            }
        }
        __syncthreads();

        // --- GEMM: acc[px][ocpair] += S[c][px] * WS[c][oc] (packed f32x2) ---
#pragma unroll 16
        for (int c = 0; c < CIN; ++c) {
            float2 sv = *(const float2*)&S[c * 64 + 2 * pp];
            unsigned long long s0 = pack2(sv.x, sv.x);
            unsigned long long s1 = pack2(sv.y, sv.y);
            const ulonglong2* wp = (const ulonglong2*)&WS[c * COUT + oc0];
            ulonglong2 wa = wp[0];
            ulonglong2 wb = wp[1];
            acc[0][0] = fma2(s0, wa.x, acc[0][0]);
            acc[0][1] = fma2(s0, wa.y, acc[0][1]);
            acc[0][2] = fma2(s0, wb.x, acc[0][2]);
            acc[0][3] = fma2(s0, wb.y, acc[0][3]);
            acc[1][0] = fma2(s1, wa.x, acc[1][0]);
            acc[1][1] = fma2(s1, wa.y, acc[1][1]);
            acc[1][2] = fma2(s1, wb.x, acc[1][2]);
            acc[1][3] = fma2(s1, wb.y, acc[1][3]);
        }
        __syncthreads();
    }

    // --- epilogue: folded bias + relu ---
    int obase = (b * COUT + oc0) * HW + row * WW + col0 + 2 * pp;
#pragma unroll
    for (int q = 0; q < 4; ++q) {
        float r0lo, r0hi, r1lo, r1hi;
        unpack2(acc[0][q], r0lo, r0hi);   // px 2pp,   oc 2q / 2q+1
        unpack2(acc[1][q], r1lo, r1hi);   // px 2pp+1, oc 2q / 2q+1
        float blo = g_bias2[oc0 + 2 * q];
        float bhi = g_bias2[oc0 + 2 * q + 1];
        out[obase + (2 * q) * HW + 0]     = fmaxf(r0lo + blo, 0.0f);
        out[obase + (2 * q) * HW + 1]     = fmaxf(r1lo + blo, 0.0f);
        out[obase + (2 * q + 1) * HW + 0] = fmaxf(r0hi + bhi, 0.0f);
        out[obase + (2 * q + 1) * HW + 1] = fmaxf(r1hi + bhi, 0.0f);
    }
}

// ---------------- launch ----------------
extern "C" void kernel_launch(void* const* d_in, const int* in_sizes, int n_in,
                              void* d_out, int out_size) {
    const float* x        = (const float*)d_in[0];
    const float* w_off    = (const float*)d_in[1];
    const float* b_off    = (const float*)d_in[2];
    const float* weight   = (const float*)d_in[3];
    const float* bias     = (const float*)d_in[4];
    const float* gamma    = (const float*)d_in[5];
    const float* beta     = (const float*)d_in[6];
    const float* run_mean = (const float*)d_in[7];
    const float* run_var  = (const float*)d_in[8];
    float* out = (float*)d_out;

    prep_kernel<<<(KT * CIN * COUT + 255) / 256, 256>>>(weight, bias, gamma, beta,
                                                        run_mean, run_var);

    cudaFuncSetAttribute(offset_conv_kernel,
                         cudaFuncAttributeMaxDynamicSharedMemorySize, 576 * 28 * 4);
    offset_conv_kernel<<<(BB * HW) / 256, 256, 576 * 28 * 4>>>(x, w_off, b_off);

    dcn_main_kernel<<<(BB * HW) / 64, 256>>>(x, out);
}

// round 5
// speedup vs baseline: 1.7537x; 1.5020x over previous
#include <cuda_runtime.h>
#include <cuda_bf16.h>
#include <math.h>
#include <stdint.h>

#define HH 128
#define WW 128
#define CIN 64
#define COUT 64
#define BB 2
#define KT 9
#define HW (HH*WW)

// ---------------- scratch (device globals; no allocation) ----------------
__device__ __align__(16) float g_offy[BB * KT * HW];
__device__ __align__(16) float g_offx[BB * KT * HW];
__device__ __align__(16) float g_mask[BB * KT * HW];
__device__ __align__(16) float g_xT[BB * HW * CIN];            // NHWC
__device__ __align__(16) __nv_bfloat16 g_wh[KT * COUT * CIN];  // [k][o][c] hi (BN folded)
__device__ __align__(16) __nv_bfloat16 g_wl[KT * COUT * CIN];  // lo
__device__ float g_bias2[COUT];

// ---------------- helpers ----------------
__device__ __forceinline__ uint32_t smem_u32(const void* p) {
    uint32_t a;
    asm("{ .reg .u64 t; cvta.to.shared.u64 t, %1; cvt.u32.u64 %0, t; }" : "=r"(a) : "l"(p));
    return a;
}
__device__ __forceinline__ unsigned long long pack2(float lo, float hi) {
    unsigned long long r;
    asm("mov.b64 %0, {%1, %2};" : "=l"(r) : "f"(lo), "f"(hi));
    return r;
}
__device__ __forceinline__ void unpack2(unsigned long long v, float& lo, float& hi) {
    asm("mov.b64 {%0, %1}, %2;" : "=f"(lo), "=f"(hi) : "l"(v));
}
__device__ __forceinline__ unsigned long long fma2(unsigned long long a,
                                                   unsigned long long b,
                                                   unsigned long long c) {
    unsigned long long d;
    asm("fma.rn.f32x2 %0, %1, %2, %3;" : "=l"(d) : "l"(a), "l"(b), "l"(c));
    return d;
}

__device__ __forceinline__ void ldm_x4(uint32_t& r0, uint32_t& r1, uint32_t& r2, uint32_t& r3,
                                       uint32_t addr) {
    asm volatile("ldmatrix.sync.aligned.m8n8.x4.shared.b16 {%0,%1,%2,%3}, [%4];"
        : "=r"(r0), "=r"(r1), "=r"(r2), "=r"(r3) : "r"(addr));
}
__device__ __forceinline__ void ldm_x2(uint32_t& r0, uint32_t& r1, uint32_t addr) {
    asm volatile("ldmatrix.sync.aligned.m8n8.x2.shared.b16 {%0,%1}, [%2];"
        : "=r"(r0), "=r"(r1) : "r"(addr));
}
__device__ __forceinline__ void mma16816(float* d,
                                         uint32_t a0, uint32_t a1, uint32_t a2, uint32_t a3,
                                         uint32_t b0, uint32_t b1) {
    asm volatile(
        "mma.sync.aligned.m16n8k16.row.col.f32.bf16.bf16.f32 "
        "{%0,%1,%2,%3}, {%4,%5,%6,%7}, {%8,%9}, {%0,%1,%2,%3};"
        : "+f"(d[0]), "+f"(d[1]), "+f"(d[2]), "+f"(d[3])
        : "r"(a0), "r"(a1), "r"(a2), "r"(a3), "r"(b0), "r"(b1));
}

// ---------------- prep: fold BN; bf16 hi/lo W [k][o][c] ----------------
__global__ void prep_kernel(const float* __restrict__ weight,
                            const float* __restrict__ bias,
                            const float* __restrict__ gamma,
                            const float* __restrict__ beta,
                            const float* __restrict__ run_mean,
                            const float* __restrict__ run_var) {
    int idx = blockIdx.x * blockDim.x + threadIdx.x;
    if (idx < COUT) {
        float inv = gamma[idx] * rsqrtf(run_var[idx] + 1e-5f);
        g_bias2[idx] = (bias[idx] - run_mean[idx]) * inv + beta[idx];
    }
    if (idx < KT * CIN * COUT) {
        int k = idx >> 12;
        int c = (idx >> 6) & 63;
        int o = idx & 63;
        float inv = gamma[o] * rsqrtf(run_var[o] + 1e-5f);
        float val = weight[(o * CIN + c) * KT + k] * inv;
        __nv_bfloat16 hi = __float2bfloat16_rn(val);
        __nv_bfloat16 lo = __float2bfloat16_rn(val - __bfloat162float(hi));
        g_wh[k * 4096 + o * 64 + c] = hi;
        g_wl[k * 4096 + o * 64 + c] = lo;
    }
}

// ---------------- transpose x: NCHW -> NHWC ----------------
__global__ void transpose_kernel(const float* __restrict__ x) {
    __shared__ float t[32][33];
    int bid = blockIdx.x;
    int ct = bid & 1;
    int pt = (bid >> 1) & 511;
    int b = bid >> 10;
    int c0 = ct * 32, p0 = pt * 32;
    int tid = threadIdx.x;

#pragma unroll
    for (int pass = 0; pass < 4; ++pass) {
        int cl = (tid >> 5) + pass * 8;
        t[cl][tid & 31] = x[(b * CIN + c0 + cl) * HW + p0 + (tid & 31)];
    }
    __syncthreads();
    int p = tid >> 3, cc = tid & 7;
    float4 v = make_float4(t[cc * 4 + 0][p], t[cc * 4 + 1][p],
                           t[cc * 4 + 2][p], t[cc * 4 + 3][p]);
    *(float4*)&g_xT[(b * HW + p0 + p) * CIN + c0 + cc * 4] = v;
}

// ---------------- offset conv: 3x3, 64 -> 27 ch, pad 1 (FFMA2) ----------------
__global__ void offset_conv_kernel(const float* __restrict__ x,
                                   const float* __restrict__ w_off,
                                   const float* __restrict__ b_off) {
    extern __shared__ float ws[];   // 576 * 28 floats = 64512 B
    int tid = threadIdx.x;

    for (int i = tid; i < 27 * CIN * 9; i += 256) {
        int oc = i / (CIN * 9);
        int rem = i - oc * (CIN * 9);
        int c = rem / 9;
        int t = rem - c * 9;
        ws[(c * 9 + t) * 28 + oc] = w_off[i];
    }
    for (int i = tid; i < 576; i += 256) ws[i * 28 + 27] = 0.0f;
    __syncthreads();

    int pid = blockIdx.x * 256 + tid;
    int b = pid >> 14;
    int h = (pid >> 7) & 127;
    int w = pid & 127;

    unsigned long long acc2[14];
#pragma unroll
    for (int q = 0; q < 14; ++q) {
        float lo = __ldg(&b_off[2 * q]);
        float hi = (2 * q + 1 < 27) ? __ldg(&b_off[2 * q + 1]) : 0.0f;
        acc2[q] = pack2(lo, hi);
    }

    const float* xb = x + b * (CIN * HW);
    for (int c = 0; c < CIN; ++c) {
        const float* xc = xb + c * HW;
        float xv[9];
#pragma unroll
        for (int ty = 0; ty < 3; ++ty) {
#pragma unroll
            for (int tx = 0; tx < 3; ++tx) {
                int hh = h + ty - 1;
                int www = w + tx - 1;
                bool ok = (hh >= 0) & (hh < HH) & (www >= 0) & (www < WW);
                xv[ty * 3 + tx] = ok ? __ldg(&xc[hh * WW + www]) : 0.0f;
            }
        }
#pragma unroll
        for (int t = 0; t < 9; ++t) {
            unsigned long long vv = pack2(xv[t], xv[t]);
            const ulonglong2* w2 = (const ulonglong2*)&ws[(c * 9 + t) * 28];
#pragma unroll
            for (int q = 0; q < 7; ++q) {
                ulonglong2 wp = w2[q];
                acc2[2 * q + 0] = fma2(vv, wp.x, acc2[2 * q + 0]);
                acc2[2 * q + 1] = fma2(vv, wp.y, acc2[2 * q + 1]);
            }
        }
    }

    float acc[28];
#pragma unroll
    for (int q = 0; q < 14; ++q) unpack2(acc2[q], acc[2 * q], acc[2 * q + 1]);

    int base = (b * KT) * HW + h * WW + w;
#pragma unroll
    for (int k = 0; k < KT; ++k) {
        g_offy[base + k * HW] = acc[2 * k];
        g_offx[base + k * HW] = acc[2 * k + 1];
        float z = acc[18 + k];
        g_mask[base + k * HW] = 1.0f / (1.0f + __expf(-z));
    }
}

// ---------------- main: gather (NHWC) + mma.sync bf16 hi/lo + bias + relu ----------------
// block = 128 px (one row), 256 threads = 8 warps.
// GEMM: A = S[px][ch] (m=px, row-major), B = W[oc][ch] (k x n col-major), D = [px][oc].
// warp w: px quarter = (w&3)*32 (2 m-tiles of 16), oc half = (w>>2)*32 (4 n-tiles of 8).
#define PADC 72
#define SM_AHI   0
#define SM_ALO   18432
#define SM_WHI   36864
#define SM_WLO   46080
#define SM_CW    55296
#define SM_CA    57344
#define SM_TOTAL 59392

__global__ void __launch_bounds__(256) dcn_main_kernel(float* __restrict__ out) {
    extern __shared__ char sm[];
    uint32_t smb = smem_u32(sm);
    int tid = threadIdx.x;
    int wid = tid >> 5;
    int lane = tid & 31;

    int b = blockIdx.x >> 7;
    int row = blockIdx.x & 127;

    int pxq = wid & 3;        // px quarter: px0 = pxq*32
    int ocg2 = wid >> 2;      // oc half:  oc0 = ocg2*32

    float acc[2][4][4];
#pragma unroll
    for (int mt = 0; mt < 2; ++mt)
#pragma unroll
        for (int nt = 0; nt < 4; ++nt)
#pragma unroll
            for (int i = 0; i < 4; ++i) acc[mt][nt][i] = 0.0f;

    float* cw = (float*)(sm + SM_CW);
    int* ca = (int*)(sm + SM_CA);
    const float4* xq = (const float4*)(g_xT + b * (HW * CIN));

    // ldmatrix byte offsets (within tile, before hi/lo base + k-step advance)
    // A (S tile): lanes 0-15 -> px rows, lanes 16-31 -> +16B (k+8)
    uint32_t a_off[2];
#pragma unroll
    for (int mt = 0; mt < 2; ++mt)
        a_off[mt] = (uint32_t)((pxq * 32 + mt * 16 + (lane & 15)) * (PADC * 2)
                               + (lane >> 4) * 16);
    // B (W tile): lanes 0-7 -> oc rows @ch0, lanes 8-15 -> oc rows @ch0+8
    int l15 = lane & 15;
    uint32_t b_off[4];
#pragma unroll
    for (int nt = 0; nt < 4; ++nt)
        b_off[nt] = (uint32_t)((ocg2 * 32 + nt * 8 + (l15 & 7)) * (PADC * 2)
                               + ((l15 >> 3) & 1) * 16);

#pragma unroll 1
    for (int k = 0; k < KT; ++k) {
        // ---- phase 1: coords (tid<128) | W tile copy (tid>=128) ----
        if (tid < 128) {
            int px = tid;
            int off_idx = (b * KT + k) * HW + row * WW + px;
            float oy = g_offy[off_idx];
            float ox = g_offx[off_idx];
            float m  = g_mask[off_idx];
            float py = (float)(row - 1 + k / 3) + oy;
            float pxx = (float)(px - 1 + k % 3) + ox;
            float y0f = floorf(py), x0f = floorf(pxx);
            float ly = py - y0f, lx = pxx - x0f;
            int y0 = (int)y0f, x0 = (int)x0f;
            float vy0 = (y0 >= 0 && y0 < HH) ? 1.0f : 0.0f;
            float vy1 = (y0 + 1 >= 0 && y0 + 1 < HH) ? 1.0f : 0.0f;
            float vx0 = (x0 >= 0 && x0 < WW) ? 1.0f : 0.0f;
            float vx1 = (x0 + 1 >= 0 && x0 + 1 < WW) ? 1.0f : 0.0f;
            float4 wv;
            wv.x = (1.0f - ly) * (1.0f - lx) * m * vy0 * vx0;
            wv.y = (1.0f - ly) * lx * m * vy0 * vx1;
            wv.z = ly * (1.0f - lx) * m * vy1 * vx0;
            wv.w = ly * lx * m * vy1 * vx1;
            int yc0 = min(max(y0, 0), HH - 1);
            int yc1 = min(max(y0 + 1, 0), HH - 1);
            int xc0 = min(max(x0, 0), WW - 1);
            int xc1 = min(max(x0 + 1, 0), WW - 1);
            int4 av;
            av.x = (yc0 * WW + xc0) * 16;   // float4-quad index into xT image
            av.y = (yc0 * WW + xc1) * 16;
            av.z = (yc1 * WW + xc0) * 16;
            av.w = (yc1 * WW + xc1) * 16;
            *(float4*)&cw[px * 4] = wv;
            *(int4*)&ca[px * 4] = av;
        } else {
            int i = tid - 128;
            const uint4* wh = (const uint4*)(g_wh + k * 4096);
            const uint4* wl = (const uint4*)(g_wl + k * 4096);
#pragma unroll
            for (int j = 0; j < 4; ++j) {
                int idx2 = i + j * 128;      // chunk 0..511
                int o = idx2 >> 3, cc = idx2 & 7;
                *(uint4*)(sm + SM_WHI + o * (PADC * 2) + cc * 16) = wh[idx2];
                *(uint4*)(sm + SM_WLO + o * (PADC * 2) + cc * 16) = wl[idx2];
            }
        }
        __syncthreads();

        // ---- phase 2: gather + hi/lo convert + store to S tiles [px][ch] ----
        int q = tid & 15;                 // channel quad (4 ch)
#pragma unroll 1
        for (int r = 0; r < 8; ++r) {
            int px = r * 16 + (tid >> 4);
            float4 wv = *(const float4*)&cw[px * 4];
            int4 av = *(const int4*)&ca[px * 4];
            float4 v00 = xq[av.x + q];
            float4 v01 = xq[av.y + q];
            float4 v10 = xq[av.z + q];
            float4 v11 = xq[av.w + q];
            float4 v;
            v.x = wv.x * v00.x + wv.y * v01.x + wv.z * v10.x + wv.w * v11.x;
            v.y = wv.x * v00.y + wv.y * v01.y + wv.z * v10.y + wv.w * v11.y;
            v.z = wv.x * v00.z + wv.y * v01.z + wv.z * v10.z + wv.w * v11.z;
            v.w = wv.x * v00.w + wv.y * v01.w + wv.z * v10.w + wv.w * v11.w;

            __nv_bfloat16 hx = __float2bfloat16_rn(v.x);
            __nv_bfloat16 hy = __float2bfloat16_rn(v.y);
            __nv_bfloat16 hz = __float2bfloat16_rn(v.z);
            __nv_bfloat16 hw = __float2bfloat16_rn(v.w);
            __nv_bfloat16 lx2 = __float2bfloat16_rn(v.x - __bfloat162float(hx));
            __nv_bfloat16 ly2 = __float2bfloat16_rn(v.y - __bfloat162float(hy));
            __nv_bfloat16 lz2 = __float2bfloat16_rn(v.z - __bfloat162float(hz));
            __nv_bfloat16 lw2 = __float2bfloat16_rn(v.w - __bfloat162float(hw));
            uint2 hi2, lo2;
            hi2.x = (uint32_t)__bfloat16_as_ushort(hx) | ((uint32_t)__bfloat16_as_ushort(hy) << 16);
            hi2.y = (uint32_t)__bfloat16_as_ushort(hz) | ((uint32_t)__bfloat16_as_ushort(hw) << 16);
            lo2.x = (uint32_t)__bfloat16_as_ushort(lx2) | ((uint32_t)__bfloat16_as_ushort(ly2) << 16);
            lo2.y = (uint32_t)__bfloat16_as_ushort(lz2) | ((uint32_t)__bfloat16_as_ushort(lw2) << 16);

            *(uint2*)(sm + SM_AHI + px * (PADC * 2) + q * 8) = hi2;
            *(uint2*)(sm + SM_ALO + px * (PADC * 2) + q * 8) = lo2;
        }
        __syncthreads();

        // ---- phase 3: mma — 3 passes (Sh*Wh, Sh*Wl, Sl*Wh) x 4 k16-steps ----
#pragma unroll
        for (int pass = 0; pass < 3; ++pass) {
            uint32_t wbase = smb + ((pass == 1) ? SM_WLO : SM_WHI);
            uint32_t sbase = smb + ((pass == 2) ? SM_ALO : SM_AHI);
#pragma unroll
            for (int ks = 0; ks < 4; ++ks) {
                uint32_t a[2][4];
#pragma unroll
                for (int mt = 0; mt < 2; ++mt)
                    ldm_x4(a[mt][0], a[mt][1], a[mt][2], a[mt][3],
                           sbase + a_off[mt] + ks * 32);
                uint32_t bf[4][2];
#pragma unroll
                for (int nt = 0; nt < 4; ++nt)
                    ldm_x2(bf[nt][0], bf[nt][1], wbase + b_off[nt] + ks * 32);
#pragma unroll
                for (int mt = 0; mt < 2; ++mt)
#pragma unroll
                    for (int nt = 0; nt < 4; ++nt)
                        mma16816(acc[mt][nt], a[mt][0], a[mt][1], a[mt][2], a[mt][3],
                                 bf[nt][0], bf[nt][1]);
            }
        }
        __syncthreads();
    }

    // ---- epilogue: bias + relu ----
    // D fragment (m16n8): d0,d1 = (px = l/4,     oc = 2*(l%4) + {0,1})
    //                     d2,d3 = (px = l/4 + 8, oc = 2*(l%4) + {0,1})
    int obase = b * COUT * HW + row * WW;
#pragma unroll
    for (int mt = 0; mt < 2; ++mt) {
        int px = pxq * 32 + mt * 16 + (lane >> 2);
#pragma unroll
        for (int nt = 0; nt < 4; ++nt) {
            int oc = ocg2 * 32 + nt * 8 + (lane & 3) * 2;
            float b0 = __ldg(&g_bias2[oc]);
            float b1 = __ldg(&g_bias2[oc + 1]);
            out[obase + oc * HW + px]           = fmaxf(acc[mt][nt][0] + b0, 0.0f);
            out[obase + (oc + 1) * HW + px]     = fmaxf(acc[mt][nt][1] + b1, 0.0f);
            out[obase + oc * HW + px + 8]       = fmaxf(acc[mt][nt][2] + b0, 0.0f);
            out[obase + (oc + 1) * HW + px + 8] = fmaxf(acc[mt][nt][3] + b1, 0.0f);
        }
    }
}

// ---------------- launch ----------------
extern "C" void kernel_launch(void* const* d_in, const int* in_sizes, int n_in,
                              void* d_out, int out_size) {
    const float* x        = (const float*)d_in[0];
    const float* w_off    = (const float*)d_in[1];
    const float* b_off    = (const float*)d_in[2];
    const float* weight   = (const float*)d_in[3];
    const float* bias     = (const float*)d_in[4];
    const float* gamma    = (const float*)d_in[5];
    const float* beta     = (const float*)d_in[6];
    const float* run_mean = (const float*)d_in[7];
    const float* run_var  = (const float*)d_in[8];
    float* out = (float*)d_out;

    prep_kernel<<<(KT * CIN * COUT + 255) / 256, 256>>>(weight, bias, gamma, beta,
                                                        run_mean, run_var);

    transpose_kernel<<<BB * 2 * 512, 256>>>(x);

    cudaFuncSetAttribute(offset_conv_kernel,
                         cudaFuncAttributeMaxDynamicSharedMemorySize, 576 * 28 * 4);
    offset_conv_kernel<<<(BB * HW) / 256, 256, 576 * 28 * 4>>>(x, w_off, b_off);

    cudaFuncSetAttribute(dcn_main_kernel,
                         cudaFuncAttributeMaxDynamicSharedMemorySize, SM_TOTAL);
    dcn_main_kernel<<<BB * HH, 256, SM_TOTAL>>>(out);
}